// round 5
// baseline (speedup 1.0000x reference)
#include <cuda_runtime.h>

typedef unsigned long long u64;

#define D      32
#define KNN    4
#define WARPS  6
#define SPB    32
#define TILE   16    // centers per stage (double-buffered)

// ---------------- packed f32x2 helpers (sm_103a FFMA2 path) ----------------
__device__ __forceinline__ u64 fma2(u64 a, u64 b, u64 c) {
    u64 r;
    asm("fma.rn.f32x2 %0, %1, %2, %3;" : "=l"(r) : "l"(a), "l"(b), "l"(c));
    return r;
}
__device__ __forceinline__ u64 add2(u64 a, u64 b) {
    u64 r;
    asm("add.rn.f32x2 %0, %1, %2;" : "=l"(r) : "l"(a), "l"(b));
    return r;
}
__device__ __forceinline__ void unpack2(u64 a, float& lo, float& hi) {
    asm("mov.b64 {%0, %1}, %2;" : "=f"(lo), "=f"(hi) : "l"(a));
}
__device__ __forceinline__ u64 pack2(float a, float b) {
    u64 r;
    asm("mov.b64 %0, {%1, %2};" : "=l"(r) : "f"(a), "f"(b));
    return r;
}
__device__ __forceinline__ unsigned smem_u32(const void* p) {
    unsigned a;
    asm("{ .reg .u64 t; cvta.to.shared.u64 t, %1; cvt.u32.u64 %0, t; }"
        : "=r"(a) : "l"(p));
    return a;
}
#define CP16(dst, src) asm volatile("cp.async.cg.shared.global [%0], [%1], 16;" :: "r"(dst), "l"(src))
#define CP4(dst, src)  asm volatile("cp.async.ca.shared.global [%0], [%1], 4;"  :: "r"(dst), "l"(src))
#define CP_COMMIT()    asm volatile("cp.async.commit_group;")
#define CP_WAIT1()     asm volatile("cp.async.wait_group 1;")
#define CP_WAIT0()     asm volatile("cp.async.wait_group 0;")

// ---------------- scratch: per-center squared norms ----------------
__device__ float g_cnorm[4096];

__global__ void cnorm_kernel(const float* __restrict__ ctrs, int n_fcns) {
    int f = blockIdx.x * blockDim.x + threadIdx.x;
    if (f < n_fcns) {
        const float4* c4 = (const float4*)(ctrs + (size_t)f * D);
        float s = 0.0f;
#pragma unroll
        for (int j = 0; j < D / 4; j++) {
            float4 q = __ldg(c4 + j);
            s += q.x * q.x + q.y * q.y + q.z * q.z + q.w * q.w;
        }
        g_cnorm[f] = s;
    }
}

// ---------------- main fused kernel ----------------
// Block = 192 threads = 6 warps, 32 samples (lane == sample).
// Phase A: warp w scans a ~341-center shard with cp.async double-buffered
//          16-center tiles, keeping a per-lane stable top-4.
// Phase B: warp w applies models for samples {w, w+6, ...} cooperatively.
__global__ __launch_bounds__(192, 4) void pwl_kernel(
    const float* __restrict__ x,
    const float* __restrict__ ctrs,
    const float* __restrict__ wts,
    const float* __restrict__ offs,
    float* __restrict__ y,
    int n_fcns)
{
    __shared__ __align__(16) float s_ctr[WARPS][2][TILE * D];  // 24 KB
    __shared__ float s_cn[WARPS][2][TILE];
    __shared__ float s_x[SPB][D + 1];
    __shared__ float s_cd[SPB][WARPS * KNN];
    __shared__ int   s_ci[SPB][WARPS * KNN];
    __shared__ int   s_idx[SPB][KNN];

    const int lane = threadIdx.x & 31;
    const int w    = threadIdx.x >> 5;
    const int srow = blockIdx.x * SPB + lane;

    // ---- load x row: registers hold packed (-2*x); smem holds raw x ----
    u64 xp[16];
    {
        const float4* xg = (const float4*)(x + (size_t)srow * D);
#pragma unroll
        for (int j = 0; j < 8; j++) {
            float4 q = __ldg(xg + j);
            if (w == 0) {
                s_x[lane][4 * j + 0] = q.x;
                s_x[lane][4 * j + 1] = q.y;
                s_x[lane][4 * j + 2] = q.z;
                s_x[lane][4 * j + 3] = q.w;
            }
            xp[2 * j]     = pack2(-2.0f * q.x, -2.0f * q.y);
            xp[2 * j + 1] = pack2(-2.0f * q.z, -2.0f * q.w);
        }
    }

    // ---- uneven shard bounds for this warp ----
    const int base = n_fcns / WARPS;
    const int rem  = n_fcns % WARPS;
    const int fstart = w * base + min(w, rem);
    const int fend   = fstart + base + (w < rem ? 1 : 0);

    // smem base addresses for this warp's two stages
    const unsigned ctr_s[2] = { smem_u32(&s_ctr[w][0][0]), smem_u32(&s_ctr[w][1][0]) };
    const unsigned cn_s[2]  = { smem_u32(&s_cn[w][0][0]),  smem_u32(&s_cn[w][1][0])  };

    // stage a tile of TILE centers starting at f0 (clamped) into stage b
    auto stage_tile = [&](int f0, int b) {
        // 16 centers * 128B = 2KB = 128 x 16B chunks; 4 per lane
#pragma unroll
        for (int i = 0; i < 4; i++) {
            int e  = i * 32 + lane;                       // 0..127
            int fr = min(f0 + (e >> 3), n_fcns - 1);
            CP16(ctr_s[b] + e * 16,
                 (const char*)(ctrs + (size_t)fr * D) + (e & 7) * 16);
        }
        if (lane < TILE) {
            int fr = min(f0 + lane, n_fcns - 1);
            CP4(cn_s[b] + lane * 4, (const char*)(g_cnorm + fr));
        }
        CP_COMMIT();
    };

    float bd0 = 3.4e38f, bd1 = 3.4e38f, bd2 = 3.4e38f, bd3 = 3.4e38f;
    int   bi0 = 0, bi1 = 0, bi2 = 0, bi3 = 0;

    stage_tile(fstart, 0);

    int buf = 0;
    for (int t = fstart; t < fend; t += TILE, buf ^= 1) {
        // prefetch next tile (clamped re-load of last tile when past end)
        stage_tile(min(t + TILE, fend - 1), buf ^ 1);
        CP_WAIT1();          // current tile resident (this lane's chunks)
        __syncwarp();        // ... and everyone else's

        const float* cbuf = &s_ctr[w][buf][0];
        const float* nbuf = &s_cn[w][buf][0];
        const int tile_n = min(TILE, fend - t);

#pragma unroll 2
        for (int ff = 0; ff < TILE; ff++) {
            const ulonglong2* c2 = (const ulonglong2*)(cbuf + ff * D);
            u64 a0 = 0ull, a1 = 0ull, a2 = 0ull;
            u64 a3 = (u64)__float_as_uint(nbuf[ff]);      // seed (cnorm, 0)
#pragma unroll
            for (int j = 0; j < 4; j++) {
                ulonglong2 qa = c2[2 * j];
                ulonglong2 qb = c2[2 * j + 1];
                a0 = fma2(xp[4 * j + 0], qa.x, a0);
                a1 = fma2(xp[4 * j + 1], qa.y, a1);
                a2 = fma2(xp[4 * j + 2], qb.x, a2);
                a3 = fma2(xp[4 * j + 3], qb.y, a3);
            }
            u64 r = add2(add2(a0, a1), add2(a2, a3));
            float lo, hi;
            unpack2(r, lo, hi);
            float sc = lo + hi;                // == cnorm - 2*dot (rank-equiv)
            int f = t + ff;
            if (sc < bd3 && ff < tile_n) {     // rare after warmup
                bool g0 = sc < bd0, g1 = sc < bd1, g2 = sc < bd2;
                float nb3 = g2 ? bd2 : sc;              int ni3 = g2 ? bi2 : f;
                float nb2 = g2 ? (g1 ? bd1 : sc) : bd2; int ni2 = g2 ? (g1 ? bi1 : f) : bi2;
                float nb1 = g1 ? (g0 ? bd0 : sc) : bd1; int ni1 = g1 ? (g0 ? bi0 : f) : bi1;
                bd0 = g0 ? sc : bd0;                    bi0 = g0 ? f : bi0;
                bd1 = nb1; bi1 = ni1;
                bd2 = nb2; bi2 = ni2;
                bd3 = nb3; bi3 = ni3;
            }
        }
        __syncwarp();        // tile fully consumed before it can be re-staged
    }
    CP_WAIT0();              // drain outstanding prefetches

    // ---- publish candidates, merge 24 -> 4 per sample ----
    s_cd[lane][w * KNN + 0] = bd0;  s_ci[lane][w * KNN + 0] = bi0;
    s_cd[lane][w * KNN + 1] = bd1;  s_ci[lane][w * KNN + 1] = bi1;
    s_cd[lane][w * KNN + 2] = bd2;  s_ci[lane][w * KNN + 2] = bi2;
    s_cd[lane][w * KNN + 3] = bd3;  s_ci[lane][w * KNN + 3] = bi3;
    __syncthreads();

    if (threadIdx.x < SPB) {
        const int ms = threadIdx.x;
        float cd[WARPS * KNN];
        int   ci[WARPS * KNN];
#pragma unroll
        for (int j = 0; j < WARPS * KNN; j++) {
            cd[j] = s_cd[ms][j];
            ci[j] = s_ci[ms][j];
        }
#pragma unroll
        for (int tt = 0; tt < KNN; tt++) {
            int best = 0;
#pragma unroll
            for (int j = 1; j < WARPS * KNN; j++) {
                // lexicographic (dist, idx): matches top_k tie-break
                if (cd[j] < cd[best] || (cd[j] == cd[best] && ci[j] < ci[best]))
                    best = j;
            }
            s_idx[ms][tt] = ci[best];
            cd[best] = 3.4e38f;
        }
    }
    __syncthreads();

    // ---- phase B: warp-cooperative apply ----
    // lane = (row = lane>>3 in 0..3, e4 = lane&7): covers d in {row, row+4, ...}
    // and output columns [4*e4, 4*e4+4).
    const int row = lane >> 3;
    const int e4  = lane & 7;
    const float4* offs4 = (const float4*)offs;

    for (int sb = w; sb < SPB; sb += WARPS) {
        float4 acc = make_float4(0.f, 0.f, 0.f, 0.f);
#pragma unroll
        for (int t = 0; t < KNN; t++) {
            int f = s_idx[sb][t];
            const float4* w4 = (const float4*)(wts + (size_t)f * D * D);
            const float*  cf = ctrs + (size_t)f * D;
#pragma unroll
            for (int dd = 0; dd < 8; dd++) {
                int d = dd * 4 + row;
                float4 wv = __ldg(w4 + d * 8 + e4);
                float  xc = s_x[sb][d] - __ldg(cf + d);
                acc.x = fmaf(xc, wv.x, acc.x);
                acc.y = fmaf(xc, wv.y, acc.y);
                acc.z = fmaf(xc, wv.z, acc.z);
                acc.w = fmaf(xc, wv.w, acc.w);
            }
        }
#pragma unroll
        for (int off = 8; off < 32; off <<= 1) {
            acc.x += __shfl_xor_sync(0xffffffffu, acc.x, off);
            acc.y += __shfl_xor_sync(0xffffffffu, acc.y, off);
            acc.z += __shfl_xor_sync(0xffffffffu, acc.z, off);
            acc.w += __shfl_xor_sync(0xffffffffu, acc.w, off);
        }
        if (row == 0) {
#pragma unroll
            for (int t = 0; t < KNN; t++) {
                int f = s_idx[sb][t];
                float4 ov = __ldg(offs4 + f * 8 + e4);
                acc.x += ov.x; acc.y += ov.y; acc.z += ov.z; acc.w += ov.w;
            }
            ((float4*)(y + (size_t)(blockIdx.x * SPB + sb) * D))[e4] = acc;
        }
    }
}

// ---------------- launch ----------------
extern "C" void kernel_launch(void* const* d_in, const int* in_sizes, int n_in,
                              void* d_out, int out_size)
{
    const float* x    = (const float*)d_in[0];
    const float* ctrs = (const float*)d_in[1];
    const float* wts  = (const float*)d_in[2];
    const float* offs = (const float*)d_in[3];
    float* y = (float*)d_out;

    int n_smps = in_sizes[0] / D;
    int n_fcns = in_sizes[1] / D;

    cnorm_kernel<<<(n_fcns + 255) / 256, 256>>>(ctrs, n_fcns);
    pwl_kernel<<<n_smps / SPB, 192>>>(x, ctrs, wts, offs, y, n_fcns);
}